// round 5
// baseline (speedup 1.0000x reference)
#include <cuda_runtime.h>
#include <cuda_bf16.h>
#include <cstdint>

// ============================================================================
// out[b,n,m] = <x[b,n,:], y[b,m,:]> / max(||x[b,n]|| * ||y[b,m]||, eps)
//   x, y: [8, 2048, 512] fp32 ; out: [8, 2048, 2048] fp32
//
// Round 5: bf16 Markidis 3-pass mma.sync, CTA 128x256, 512 threads.
//   - BK=32 with paired-row swizzle (2x 64B rows per 128B line) -> 48KB/stage
//   - 4-stage cp.async ring, ONE __syncthreads per k-iter, loads issued
//     right after the barrier (2-3 stages in flight at all times)
//   - MMA passes grouped to break accumulator RAW chains
// ============================================================================

#define Bq 8
#define Nq 2048
#define Dq 512
#define EPSq 1e-8f

#define BMq 128
#define BNq 256
#define BKq 32                 // k per stage (32 bf16 = 64B per row)
#define NSTAGE 4
#define KITER (Dq / BKq)       // 16

// per-stage: Ahi 8K | Alo 8K | Bhi 16K | Blo 16K = 48KB
#define A_HI_OFF   0
#define A_LO_OFF   8192
#define B_HI_OFF   16384
#define B_LO_OFF   32768
#define STG_BYTES  49152
#define SMEM_TOTAL (NSTAGE * STG_BYTES)   // 196608

__device__ float g_xn[Bq * Nq];
__device__ float g_yn[Bq * Nq];
__device__ __nv_bfloat16 g_xhi[Bq * Nq * Dq];
__device__ __nv_bfloat16 g_xlo[Bq * Nq * Dq];
__device__ __nv_bfloat16 g_yhi[Bq * Nq * Dq];
__device__ __nv_bfloat16 g_ylo[Bq * Nq * Dq];

// ---------------------------------------------------------------------------
__device__ __forceinline__ uint32_t smem_u32(const void* p) {
    uint32_t a;
    asm("{ .reg .u64 t; cvta.to.shared.u64 t, %1; cvt.u32.u64 %0, t; }"
        : "=r"(a) : "l"(p));
    return a;
}

#define CP_ASYNC16(dst, src) \
    asm volatile("cp.async.cg.shared.global [%0], [%1], 16;" \
                 :: "r"(dst), "l"(src) : "memory")
#define CP_COMMIT() asm volatile("cp.async.commit_group;" ::: "memory")
#define CP_WAIT2()  asm volatile("cp.async.wait_group 2;" ::: "memory")

#define LDSM4(r, addr) \
    asm volatile("ldmatrix.sync.aligned.m8n8.x4.shared.b16 {%0,%1,%2,%3}, [%4];" \
                 : "=r"((r)[0]), "=r"((r)[1]), "=r"((r)[2]), "=r"((r)[3]) \
                 : "r"(addr))

#define MMA16816(d, a, bf) \
    asm volatile("mma.sync.aligned.m16n8k16.row.col.f32.bf16.bf16.f32 " \
                 "{%0,%1,%2,%3}, {%4,%5,%6,%7}, {%8,%9}, {%0,%1,%2,%3};" \
                 : "+f"((d)[0]), "+f"((d)[1]), "+f"((d)[2]), "+f"((d)[3]) \
                 : "r"((a)[0]), "r"((a)[1]), "r"((a)[2]), "r"((a)[3]), \
                   "r"((bf)[0]), "r"((bf)[1]))

// paired-row swizzle: row r (64B of data), 16B chunk c (0..3)
//   line  = r >> 1 (128B lines), c_eff = (r&1)*4 + c, addr = line*128 + ((c_eff ^ (line&7))<<4)
__device__ __forceinline__ uint32_t swz_off(int r, int c) {
    uint32_t line = (uint32_t)r >> 1;
    uint32_t ce = (((uint32_t)r & 1u) << 2) | (uint32_t)c;
    return line * 128u + ((ce ^ (line & 7u)) << 4);
}

// ---------------------------------------------------------------------------
// Prep: one warp per row (x row + y row): norms + hi/lo bf16 split.
// ---------------------------------------------------------------------------
__global__ void __launch_bounds__(256) prep_kernel(const float* __restrict__ X,
                                                   const float* __restrict__ Y) {
    int row = blockIdx.x * 8 + (threadIdx.x >> 5);
    int lane = threadIdx.x & 31;
    if (row >= Bq * Nq) return;

    const float4* px = reinterpret_cast<const float4*>(X + (size_t)row * Dq);
    const float4* py = reinterpret_cast<const float4*>(Y + (size_t)row * Dq);

    float sx = 0.f, sy = 0.f;
#pragma unroll
    for (int v = 0; v < 4; v++) {
        int i = v * 32 + lane;
        {
            float4 a = px[i];
            sx = fmaf(a.x, a.x, sx); sx = fmaf(a.y, a.y, sx);
            sx = fmaf(a.z, a.z, sx); sx = fmaf(a.w, a.w, sx);
            __nv_bfloat162 h0 = __floats2bfloat162_rn(a.x, a.y);
            __nv_bfloat162 h1 = __floats2bfloat162_rn(a.z, a.w);
            __nv_bfloat162 l0 = __floats2bfloat162_rn(a.x - __bfloat162float(h0.x),
                                                      a.y - __bfloat162float(h0.y));
            __nv_bfloat162 l1 = __floats2bfloat162_rn(a.z - __bfloat162float(h1.x),
                                                      a.w - __bfloat162float(h1.y));
            size_t off = (size_t)row * Dq + (size_t)i * 4;
            *reinterpret_cast<__nv_bfloat162*>(g_xhi + off)     = h0;
            *reinterpret_cast<__nv_bfloat162*>(g_xhi + off + 2) = h1;
            *reinterpret_cast<__nv_bfloat162*>(g_xlo + off)     = l0;
            *reinterpret_cast<__nv_bfloat162*>(g_xlo + off + 2) = l1;
        }
        {
            float4 a = py[i];
            sy = fmaf(a.x, a.x, sy); sy = fmaf(a.y, a.y, sy);
            sy = fmaf(a.z, a.z, sy); sy = fmaf(a.w, a.w, sy);
            __nv_bfloat162 h0 = __floats2bfloat162_rn(a.x, a.y);
            __nv_bfloat162 h1 = __floats2bfloat162_rn(a.z, a.w);
            __nv_bfloat162 l0 = __floats2bfloat162_rn(a.x - __bfloat162float(h0.x),
                                                      a.y - __bfloat162float(h0.y));
            __nv_bfloat162 l1 = __floats2bfloat162_rn(a.z - __bfloat162float(h1.x),
                                                      a.w - __bfloat162float(h1.y));
            size_t off = (size_t)row * Dq + (size_t)i * 4;
            *reinterpret_cast<__nv_bfloat162*>(g_yhi + off)     = h0;
            *reinterpret_cast<__nv_bfloat162*>(g_yhi + off + 2) = h1;
            *reinterpret_cast<__nv_bfloat162*>(g_ylo + off)     = l0;
            *reinterpret_cast<__nv_bfloat162*>(g_ylo + off + 2) = l1;
        }
    }
#pragma unroll
    for (int off = 16; off > 0; off >>= 1) {
        sx += __shfl_xor_sync(0xFFFFFFFFu, sx, off);
        sy += __shfl_xor_sync(0xFFFFFFFFu, sy, off);
    }
    if (lane == 0) {
        g_xn[row] = sqrtf(sx);
        g_yn[row] = sqrtf(sy);
    }
}

// ---------------------------------------------------------------------------
// cp.async one stage (BK=32): A 128 rows x 4 chunks, B 256 rows x 4 chunks.
// 512 threads: A hi/lo 1 chunk each, B hi/lo 2 chunks each.
// ---------------------------------------------------------------------------
__device__ __forceinline__ void load_stage(uint32_t sb_stage, int kt,
                                           int rowA0, int rowB0, int b, int tid) {
    const size_t kbase = (size_t)kt * BKq;
    {
        int r = tid >> 2;                 // 0..127
        int c = tid & 3;
        uint32_t doff = swz_off(r, c);
        size_t off = ((size_t)(b * Nq + rowA0 + r)) * Dq + kbase + c * 8;
        CP_ASYNC16(sb_stage + A_HI_OFF + doff, g_xhi + off);
        CP_ASYNC16(sb_stage + A_LO_OFF + doff, g_xlo + off);
    }
#pragma unroll
    for (int i = 0; i < 2; i++) {
        int idx = tid + i * 512;          // 0..1023
        int r = idx >> 2;                 // 0..255
        int c = idx & 3;
        uint32_t doff = swz_off(r, c);
        size_t off = ((size_t)(b * Nq + rowB0 + r)) * Dq + kbase + c * 8;
        CP_ASYNC16(sb_stage + B_HI_OFF + doff, g_yhi + off);
        CP_ASYNC16(sb_stage + B_LO_OFF + doff, g_ylo + off);
    }
}

// ---------------------------------------------------------------------------
// GEMM kernel. Grid (8,16,8), 512 threads = 16 warps (2 x 8), warp tile 64x32.
// ---------------------------------------------------------------------------
__global__ void __launch_bounds__(512, 1) cosine_mma_kernel(float* __restrict__ out) {
    extern __shared__ char smem[];
    const uint32_t sb = smem_u32(smem);

    const int tid = threadIdx.x;
    const int wid = tid >> 5, lane = tid & 31;
    const int wm = wid >> 3;          // 0..1  (64 m-rows)
    const int wn = wid & 7;           // 0..7  (32 n-cols)
    const int tileM = blockIdx.x;
    const int tileN = blockIdx.y;
    const int b = blockIdx.z;
    const int rowA0 = tileN * BMq;
    const int rowB0 = tileM * BNq;

    float acc[4][4][4];
#pragma unroll
    for (int i = 0; i < 4; i++)
#pragma unroll
        for (int j = 0; j < 4; j++)
#pragma unroll
            for (int r = 0; r < 4; r++) acc[i][j][r] = 0.f;

    // prologue: 3 stages in flight
    load_stage(sb + 0 * STG_BYTES, 0, rowA0, rowB0, b, tid); CP_COMMIT();
    load_stage(sb + 1 * STG_BYTES, 1, rowA0, rowB0, b, tid); CP_COMMIT();
    load_stage(sb + 2 * STG_BYTES, 2, rowA0, rowB0, b, tid); CP_COMMIT();

    const int rowSel = (lane & 7) + ((lane >> 3 & 1) << 3);  // 0..15
    const int kcq = lane >> 4;                               // 0/1

    // hoisted per-lane swizzle pieces: addr = lineT + (((par|kc) ^ swz) << 4)
    uint32_t aLineT[4], aPar[4], aSwz[4];
#pragma unroll
    for (int mi = 0; mi < 4; mi++) {
        int row = wm * 64 + mi * 16 + rowSel;
        aLineT[mi] = (uint32_t)(row >> 1) * 128u;
        aPar[mi] = ((uint32_t)row & 1u) << 2;
        aSwz[mi] = (uint32_t)(row >> 1) & 7u;
    }
    uint32_t bLineT[2], bPar[2], bSwz[2];
#pragma unroll
    for (int nj = 0; nj < 2; nj++) {
        int row = wn * 32 + nj * 16 + rowSel;
        bLineT[nj] = (uint32_t)(row >> 1) * 128u;
        bPar[nj] = ((uint32_t)row & 1u) << 2;
        bSwz[nj] = (uint32_t)(row >> 1) & 7u;
    }

    for (int t = 0; t < KITER; t++) {
        CP_WAIT2();
        __syncthreads();
        if (t + 3 < KITER)
            load_stage(sb + ((t + 3) & 3) * STG_BYTES, t + 3, rowA0, rowB0, b, tid);
        CP_COMMIT();

        const uint32_t st = sb + (t & 3) * STG_BYTES;
        const uint32_t sAhi = st + A_HI_OFF, sAlo = st + A_LO_OFF;
        const uint32_t sBhi = st + B_HI_OFF, sBlo = st + B_LO_OFF;

#pragma unroll
        for (int k16 = 0; k16 < 2; k16++) {
            const uint32_t kc = (uint32_t)(k16 * 2 + kcq);   // 0..3
            uint32_t b_hi[4][2], b_lo[4][2];
#pragma unroll
            for (int nj = 0; nj < 2; nj++) {
                uint32_t off = bLineT[nj] + (((bPar[nj] | kc) ^ bSwz[nj]) << 4);
                uint32_t th[4], tl[4];
                LDSM4(th, sBhi + off);
                LDSM4(tl, sBlo + off);
                b_hi[2 * nj][0] = th[0]; b_hi[2 * nj + 1][0] = th[1];
                b_hi[2 * nj][1] = th[2]; b_hi[2 * nj + 1][1] = th[3];
                b_lo[2 * nj][0] = tl[0]; b_lo[2 * nj + 1][0] = tl[1];
                b_lo[2 * nj][1] = tl[2]; b_lo[2 * nj + 1][1] = tl[3];
            }
#pragma unroll
            for (int mi = 0; mi < 4; mi++) {
                uint32_t a_hi[4], a_lo[4];
                uint32_t off = aLineT[mi] + (((aPar[mi] | kc) ^ aSwz[mi]) << 4);
                LDSM4(a_hi, sAhi + off);
                LDSM4(a_lo, sAlo + off);
                // pass-grouped: accumulator RAW distance = 4
#pragma unroll
                for (int ni = 0; ni < 4; ni++) MMA16816(acc[mi][ni], a_hi, b_hi[ni]);
#pragma unroll
                for (int ni = 0; ni < 4; ni++) MMA16816(acc[mi][ni], a_hi, b_lo[ni]);
#pragma unroll
                for (int ni = 0; ni < 4; ni++) MMA16816(acc[mi][ni], a_lo, b_hi[ni]);
            }
        }
    }

    // ---- fused cosine epilogue ----
    const int gq = lane >> 2;
    const int tq = lane & 3;

    float yv0[4], yv1[4];
#pragma unroll
    for (int ni = 0; ni < 4; ni++) {
        int n = rowB0 + wn * 32 + ni * 8 + 2 * tq;
        yv0[ni] = g_yn[b * Nq + n];
        yv1[ni] = g_yn[b * Nq + n + 1];
    }

#pragma unroll
    for (int mi = 0; mi < 4; mi++) {
        int mA = rowA0 + wm * 64 + mi * 16 + gq;
        float xA = g_xn[b * Nq + mA];
        float xB = g_xn[b * Nq + mA + 8];
        float* orowA = out + ((size_t)b * Nq + mA) * Nq + rowB0 + wn * 32;
        float* orowB = orowA + 8 * (size_t)Nq;
#pragma unroll
        for (int ni = 0; ni < 4; ni++) {
            float2 vA, vB;
            vA.x = acc[mi][ni][0] / fmaxf(xA * yv0[ni], EPSq);
            vA.y = acc[mi][ni][1] / fmaxf(xA * yv1[ni], EPSq);
            vB.x = acc[mi][ni][2] / fmaxf(xB * yv0[ni], EPSq);
            vB.y = acc[mi][ni][3] / fmaxf(xB * yv1[ni], EPSq);
            *reinterpret_cast<float2*>(orowA + ni * 8 + 2 * tq) = vA;
            *reinterpret_cast<float2*>(orowB + ni * 8 + 2 * tq) = vB;
        }
    }
}

// ---------------------------------------------------------------------------
extern "C" void kernel_launch(void* const* d_in, const int* in_sizes, int n_in,
                              void* d_out, int out_size) {
    const float* x = (const float*)d_in[0];
    const float* y = (const float*)d_in[1];
    float* out = (float*)d_out;

    prep_kernel<<<(Bq * Nq + 7) / 8, 256>>>(x, y);

    cudaFuncSetAttribute(cosine_mma_kernel,
                         cudaFuncAttributeMaxDynamicSharedMemorySize, SMEM_TOTAL);
    dim3 grid(Nq / BNq, Nq / BMq, Bq);   // (8, 16, 8)
    cosine_mma_kernel<<<grid, 512, SMEM_TOTAL>>>(out);
}